// round 1
// baseline (speedup 1.0000x reference)
#include <cuda_runtime.h>

// EPS_68771016344265: 2x2 tensor-network contraction, S=2, OUT=4
// out[b,h,w,o] = sum_{s0,s1,s2,s3} x(h,w)[s0] x(h,w+1)[s1] x(h+1,w)[s2] x(h+1,w+1)[s3]
//               * core[s0,s1,s2,s3,o]
// Shapes: input (1,128,128,128,2) f32, core (2,2,2,2,4) f32, out (128,127,127,4) f32.

#define NB 128
#define NH 128
#define NW 128
#define HN 127
#define WN 127

__global__ __launch_bounds__(256)
void eps_kernel(const float* __restrict__ in,
                const float* __restrict__ core,
                float4* __restrict__ out)
{
    __shared__ float4 sc[16];   // sc[s0*8+s1*4+s2*2+s3 -> i*4+j], float4 over o
    int t = threadIdx.x;
    if (t < 16) sc[t] = reinterpret_cast<const float4*>(core)[t];
    __syncthreads();

    int idx = blockIdx.x * blockDim.x + threadIdx.x;
    const int total = NB * HN * WN;   // 2,064,512
    if (idx >= total) return;

    int w = idx % WN;
    int r = idx / WN;
    int h = r % HN;
    int b = r / HN;

    const float2* ip = reinterpret_cast<const float2*>(in);
    int base = (b * NH + h) * NW + w;   // pixel index into (b,h,w) grid of float2

    float2 x00 = ip[base];
    float2 x01 = ip[base + 1];
    float2 x10 = ip[base + NW];
    float2 x11 = ip[base + NW + 1];

    // q[i] = x00[s0]*x01[s1], i = s0*2+s1 ; p[j] = x10[s2]*x11[s3], j = s2*2+s3
    float q0 = x00.x * x01.x, q1 = x00.x * x01.y, q2 = x00.y * x01.x, q3 = x00.y * x01.y;
    float p0 = x10.x * x11.x, p1 = x10.x * x11.y, p2 = x10.y * x11.x, p3 = x10.y * x11.y;
    float q[4] = {q0, q1, q2, q3};
    float p[4] = {p0, p1, p2, p3};

    float4 acc = make_float4(0.f, 0.f, 0.f, 0.f);
    #pragma unroll
    for (int i = 0; i < 4; i++) {
        #pragma unroll
        for (int j = 0; j < 4; j++) {
            float tt = q[i] * p[j];
            float4 c = sc[i * 4 + j];
            acc.x = fmaf(tt, c.x, acc.x);
            acc.y = fmaf(tt, c.y, acc.y);
            acc.z = fmaf(tt, c.z, acc.z);
            acc.w = fmaf(tt, c.w, acc.w);
        }
    }
    out[idx] = acc;
}

extern "C" void kernel_launch(void* const* d_in, const int* in_sizes, int n_in,
                              void* d_out, int out_size)
{
    const float* in   = (const float*)d_in[0];   // (1,128,128,128,2) f32
    const float* core = (const float*)d_in[1];   // (2,2,2,2,4) f32
    float4* out = (float4*)d_out;

    const int total = NB * HN * WN;
    int block = 256;
    int grid = (total + block - 1) / block;
    eps_kernel<<<grid, block>>>(in, core, out);
}

// round 3
// speedup vs baseline: 1.1758x; 1.1758x over previous
#include <cuda_runtime.h>

// EPS_68771016344265: 2x2 tensor-network contraction, S=2, OUT=4
// out[b,h,w,o] = sum_{s0..s3} x_h[w][s0] x_h[w+1][s1] x_{h+1}[w][s2] x_{h+1}[w+1][s3]
//               * core[s0,s1,s2,s3,o]
// q(h) = x_h[w] (x) x_h[w+1]  (i = s0*2+s1);   p for pixel h == q(h+1).
// Hierarchy: d_j = sum_i q(h)_i C[i][j][:], out = sum_j q(h+1)_j d_j.
// o-dim (4 floats) packed as two f32x2 registers; core held in registers.

#define NB 128
#define NH 128
#define NW 128
#define HN 127
#define WN 127
#define TH 16

typedef unsigned long long u64;

__device__ __forceinline__ u64 f2mul(u64 a, u64 b) {
    u64 r; asm("mul.rn.f32x2 %0,%1,%2;" : "=l"(r) : "l"(a), "l"(b)); return r;
}
__device__ __forceinline__ u64 f2fma(u64 a, u64 b, u64 c) {
    u64 r; asm("fma.rn.f32x2 %0,%1,%2,%3;" : "=l"(r) : "l"(a), "l"(b), "l"(c)); return r;
}
__device__ __forceinline__ u64 fdup(float x) {
    u64 r; asm("mov.b64 %0,{%1,%1};" : "=l"(r) : "f"(x)); return r;
}
__device__ __forceinline__ float2 f2unpack(u64 a) {
    float2 v; asm("mov.b64 {%0,%1},%2;" : "=f"(v.x), "=f"(v.y) : "l"(a)); return v;
}

__global__ __launch_bounds__(128)
void eps_kernel(const float* __restrict__ in,
                const float* __restrict__ core,
                float4* __restrict__ out)
{
    const int w  = threadIdx.x;            // 0..127 (lane-coalesced loads)
    const int b  = blockIdx.y;
    const int h0 = blockIdx.x * TH;
    const int h1 = min(h0 + TH, HN);       // pixel rows [h0, h1)

    // Core in registers, packed over o: c01[k] = {core[k][0],core[k][1]}, c23 = {[2],[3]}
    u64 c01[16], c23[16];
    {
        const ulonglong2* cp = reinterpret_cast<const ulonglong2*>(core);
        #pragma unroll
        for (int k = 0; k < 16; k++) { ulonglong2 v = cp[k]; c01[k] = v.x; c23[k] = v.y; }
    }

    const float2* ip = reinterpret_cast<const float2*>(in);
    const int wp1 = (w < NW - 1) ? (w + 1) : w;    // clamp; w=127 never stores
    long rowoff = (long)(b * NH + h0) * NW;

    // ---- row h0: q and d ----
    float2 xa = ip[rowoff + w];
    float2 xb = ip[rowoff + wp1];
    u64 q0 = fdup(xa.x * xb.x);
    u64 q1 = fdup(xa.x * xb.y);
    u64 q2 = fdup(xa.y * xb.x);
    u64 q3 = fdup(xa.y * xb.y);

    u64 d01[4], d23[4];
    #pragma unroll
    for (int j = 0; j < 4; j++) {
        d01[j] = f2fma(q3, c01[12+j], f2fma(q2, c01[8+j], f2fma(q1, c01[4+j], f2mul(q0, c01[j]))));
        d23[j] = f2fma(q3, c23[12+j], f2fma(q2, c23[8+j], f2fma(q1, c23[4+j], f2mul(q0, c23[j]))));
    }

    const bool st = (w < WN);
    for (int r = h0 + 1; r <= h1; ++r) {
        rowoff += NW;
        xa = ip[rowoff + w];
        xb = ip[rowoff + wp1];
        q0 = fdup(xa.x * xb.x);
        q1 = fdup(xa.x * xb.y);
        q2 = fdup(xa.y * xb.x);
        q3 = fdup(xa.y * xb.y);

        // pixel (r-1): out = sum_j q(r)_j * d(r-1)_j
        u64 o01 = f2fma(q3, d01[3], f2fma(q2, d01[2], f2fma(q1, d01[1], f2mul(q0, d01[0]))));
        u64 o23 = f2fma(q3, d23[3], f2fma(q2, d23[2], f2fma(q1, d23[1], f2mul(q0, d23[0]))));
        if (st) {
            float2 a = f2unpack(o01), c = f2unpack(o23);
            out[(long)(b * HN + (r - 1)) * WN + w] = make_float4(a.x, a.y, c.x, c.y);
        }

        // d(r) for the next pixel (unconditional: avoids a branch; waste only on last iter)
        #pragma unroll
        for (int j = 0; j < 4; j++) {
            d01[j] = f2fma(q3, c01[12+j], f2fma(q2, c01[8+j], f2fma(q1, c01[4+j], f2mul(q0, c01[j]))));
            d23[j] = f2fma(q3, c23[12+j], f2fma(q2, c23[8+j], f2fma(q1, c23[4+j], f2mul(q0, c23[j]))));
        }
    }
}

extern "C" void kernel_launch(void* const* d_in, const int* in_sizes, int n_in,
                              void* d_out, int out_size)
{
    const float* in   = (const float*)d_in[0];   // (1,128,128,128,2) f32
    const float* core = (const float*)d_in[1];   // (2,2,2,2,4) f32
    float4* out = (float4*)d_out;                // (128,127,127,4) f32

    dim3 grid((HN + TH - 1) / TH, NB);           // (8, 128)
    eps_kernel<<<grid, 128>>>(in, core, out);
}

// round 4
// speedup vs baseline: 1.1863x; 1.0089x over previous
#include <cuda_runtime.h>

// EPS_68771016344265: 2x2 tensor-network contraction, S=2, OUT=4
// out[b,h,w,o] = sum_{s0..s3} x_h[w][s0] x_h[w+1][s1] x_{h+1}[w][s2] x_{h+1}[w+1][s3]
//               * core[s0,s1,s2,s3,o]
// q(h) = x_h[w] (x) x_h[w+1];  d(h)_j = sum_i q(h)_i C[i][j][:];  out(h) = sum_j q(h+1)_j d(h)_j
// o-dim packed as two f32x2 regs; core in registers; thread = one column, strip of TH rows.

#define NB 128
#define NH 128
#define NW 128
#define HN 127
#define WN 127
#define TH 8

typedef unsigned long long u64;

__device__ __forceinline__ u64 f2mul(u64 a, u64 b) {
    u64 r; asm("mul.rn.f32x2 %0,%1,%2;" : "=l"(r) : "l"(a), "l"(b)); return r;
}
__device__ __forceinline__ u64 f2fma(u64 a, u64 b, u64 c) {
    u64 r; asm("fma.rn.f32x2 %0,%1,%2,%3;" : "=l"(r) : "l"(a), "l"(b), "l"(c)); return r;
}
__device__ __forceinline__ u64 fdup(float x) {
    u64 r; asm("mov.b64 %0,{%1,%1};" : "=l"(r) : "f"(x)); return r;
}
__device__ __forceinline__ float2 f2unpack(u64 a) {
    float2 v; asm("mov.b64 {%0,%1},%2;" : "=f"(v.x), "=f"(v.y) : "l"(a)); return v;
}

__global__ __launch_bounds__(64, 16)
void eps_kernel(const float* __restrict__ in,
                const float* __restrict__ core,
                float4* __restrict__ out)
{
    const int w  = blockIdx.y * 64 + threadIdx.x;   // 0..127
    const int b  = blockIdx.z;
    const int h0 = blockIdx.x * TH;
    const int h1 = min(h0 + TH, HN);                // pixel rows [h0, h1)

    // Core in registers, packed over o: c01[k] = {core[k][0],core[k][1]}, c23 = {[2],[3]}
    u64 c01[16], c23[16];
    {
        const ulonglong2* cp = reinterpret_cast<const ulonglong2*>(core);
        #pragma unroll
        for (int k = 0; k < 16; k++) { ulonglong2 v = cp[k]; c01[k] = v.x; c23[k] = v.y; }
    }

    const float2* ip = reinterpret_cast<const float2*>(in);
    const int wp1 = (w < NW - 1) ? (w + 1) : w;     // clamp; w=127 never stores
    long rowoff = (long)(b * NH + h0) * NW;

    // ---- row h0: q and d ----
    float2 xa = ip[rowoff + w];
    float2 xb = ip[rowoff + wp1];
    u64 q0 = fdup(xa.x * xb.x);
    u64 q1 = fdup(xa.x * xb.y);
    u64 q2 = fdup(xa.y * xb.x);
    u64 q3 = fdup(xa.y * xb.y);

    u64 d01[4], d23[4];
    #pragma unroll
    for (int j = 0; j < 4; j++) {
        d01[j] = f2fma(q3, c01[12+j], f2fma(q2, c01[8+j], f2fma(q1, c01[4+j], f2mul(q0, c01[j]))));
        d23[j] = f2fma(q3, c23[12+j], f2fma(q2, c23[8+j], f2fma(q1, c23[4+j], f2mul(q0, c23[j]))));
    }

    const bool st = (w < WN);
    float4* outp = out + (long)(b * HN + h0) * WN + w;

    #pragma unroll
    for (int r = h0 + 1; r <= h0 + TH; ++r) {
        if (r > h1) break;                          // only the last strip exits early
        rowoff += NW;
        xa = ip[rowoff + w];
        xb = ip[rowoff + wp1];
        q0 = fdup(xa.x * xb.x);
        q1 = fdup(xa.x * xb.y);
        q2 = fdup(xa.y * xb.x);
        q3 = fdup(xa.y * xb.y);

        // pixel (r-1): out = sum_j q(r)_j * d(r-1)_j
        u64 o01 = f2fma(q3, d01[3], f2fma(q2, d01[2], f2fma(q1, d01[1], f2mul(q0, d01[0]))));
        u64 o23 = f2fma(q3, d23[3], f2fma(q2, d23[2], f2fma(q1, d23[1], f2mul(q0, d23[0]))));
        if (st) {
            float2 a = f2unpack(o01), c = f2unpack(o23);
            *outp = make_float4(a.x, a.y, c.x, c.y);
        }
        outp += WN;

        // d(r) for the next pixel (unconditional; waste only on last iteration)
        #pragma unroll
        for (int j = 0; j < 4; j++) {
            d01[j] = f2fma(q3, c01[12+j], f2fma(q2, c01[8+j], f2fma(q1, c01[4+j], f2mul(q0, c01[j]))));
            d23[j] = f2fma(q3, c23[12+j], f2fma(q2, c23[8+j], f2fma(q1, c23[4+j], f2mul(q0, c23[j]))));
        }
    }
}

extern "C" void kernel_launch(void* const* d_in, const int* in_sizes, int n_in,
                              void* d_out, int out_size)
{
    const float* in   = (const float*)d_in[0];   // (1,128,128,128,2) f32
    const float* core = (const float*)d_in[1];   // (2,2,2,2,4) f32
    float4* out = (float4*)d_out;                // (128,127,127,4) f32

    dim3 grid((HN + TH - 1) / TH, 2, NB);        // (16, 2, 128) = 4096 blocks
    eps_kernel<<<grid, 64>>>(in, core, out);
}